// round 2
// baseline (speedup 1.0000x reference)
#include <cuda_runtime.h>
#include <cstdint>

#define G_   2048
#define NPG  128
#define NN   (G_*NPG)       // 262144 nodes
#define INC  151
#define HID  64
#define NE   2097152
#define NEG_SLOPE 0.2f

// ---------------- device scratch ----------------
__device__ float g_h[(size_t)NN * HID];   // 64 MB
__device__ float g_as[NN];
__device__ float g_ad[NN];
__device__ int   g_deg[NN];
__device__ int   g_fill[NN];
__device__ int   g_off[NN];
__device__ int   g_bsum[1024];
__device__ int   g_csr[NE];
__device__ float g_logits[G_];

// ---------------- K0: zero counters ----------------
__global__ void k_zero() {
    int i = blockIdx.x * blockDim.x + threadIdx.x;
    if (i < NN) { g_deg[i] = 0; g_fill[i] = 0; }
    if (i < G_) g_logits[i] = 0.f;
}

// ---------------- tf32 helpers ----------------
__device__ __forceinline__ uint32_t f2tf(float f) {
    uint32_t r;
    asm("cvt.rna.tf32.f32 %0, %1;" : "=r"(r) : "f"(f));
    return r;
}
__device__ __forceinline__ void mma8(float* c, const uint32_t* a, const uint32_t* b) {
    asm volatile(
        "mma.sync.aligned.m16n8k8.row.col.f32.tf32.tf32.f32 "
        "{%0,%1,%2,%3},{%4,%5,%6,%7},{%8,%9},{%0,%1,%2,%3};"
        : "+f"(c[0]), "+f"(c[1]), "+f"(c[2]), "+f"(c[3])
        : "r"(a[0]), "r"(a[1]), "r"(a[2]), "r"(a[3]), "r"(b[0]), "r"(b[1]));
}

// ---------------- K1: h = x @ W1, 3xTF32 tensor-core GEMM ----------------
// Block tile 128(M) x 64(N), K chunks of 16, 8 warps in 4x2 (each 32x32).
#define LDX 20
#define LDW 72
__global__ __launch_bounds__(256, 2) void k_gemm(const float* __restrict__ x,
                                                 const float* __restrict__ W) {
    __shared__ float sX[128 * LDX];
    __shared__ float sW[16 * LDW];
    int tid = threadIdx.x, lane = tid & 31, wid = tid >> 5;
    int g = lane >> 2, tg = lane & 3;
    int warp_m = wid >> 1, warp_n = wid & 1;
    int row0 = blockIdx.x * 128;

    float acc[2][4][4] = {};

    for (int c0 = 0; c0 < 152; c0 += 16) {
        // load x tile [128 x 16]
        {
            int c = tid & 15, rt = tid >> 4;
            #pragma unroll
            for (int r = rt; r < 128; r += 16) {
                int col = c0 + c;
                sX[r * LDX + c] = (col < INC) ? x[(size_t)(row0 + r) * INC + col] : 0.f;
            }
        }
        // load W tile [16 x 64]
        {
            int n = tid & 63, kt = tid >> 6;
            #pragma unroll
            for (int k = kt; k < 16; k += 4) {
                int kk = c0 + k;
                sW[k * LDW + n] = (kk < INC) ? W[kk * 64 + n] : 0.f;
            }
        }
        __syncthreads();

        #pragma unroll
        for (int ks = 0; ks < 2; ks++) {
            int kb = ks * 8;
            // A fragments (2 m-tiles), hi/lo split
            uint32_t ahi[2][4], alo[2][4];
            #pragma unroll
            for (int tm = 0; tm < 2; tm++) {
                int rbase = warp_m * 32 + tm * 16 + g;
                #pragma unroll
                for (int i = 0; i < 4; i++) {
                    int r  = rbase + (i & 1) * 8;
                    int cc = kb + tg + (i >> 1) * 4;
                    float f  = sX[r * LDX + cc];
                    uint32_t h = f2tf(f);
                    ahi[tm][i] = h;
                    alo[tm][i] = f2tf(f - __uint_as_float(h));
                }
            }
            // B fragments (4 n-tiles), hi/lo split
            uint32_t bhi[4][2], blo[4][2];
            #pragma unroll
            for (int tn = 0; tn < 4; tn++) {
                int nb = warp_n * 32 + tn * 8 + g;
                #pragma unroll
                for (int i = 0; i < 2; i++) {
                    float f  = sW[(kb + tg + i * 4) * LDW + nb];
                    uint32_t h = f2tf(f);
                    bhi[tn][i] = h;
                    blo[tn][i] = f2tf(f - __uint_as_float(h));
                }
            }
            #pragma unroll
            for (int tm = 0; tm < 2; tm++)
                #pragma unroll
                for (int tn = 0; tn < 4; tn++) {
                    mma8(acc[tm][tn], alo[tm], bhi[tn]);
                    mma8(acc[tm][tn], ahi[tm], blo[tn]);
                    mma8(acc[tm][tn], ahi[tm], bhi[tn]);
                }
        }
        __syncthreads();
    }

    // epilogue: write h
    #pragma unroll
    for (int tm = 0; tm < 2; tm++) {
        int r = row0 + warp_m * 32 + tm * 16 + g;
        #pragma unroll
        for (int tn = 0; tn < 4; tn++) {
            int cn = warp_n * 32 + tn * 8 + 2 * tg;
            *(float2*)&g_h[(size_t)r * 64 + cn]       = make_float2(acc[tm][tn][0], acc[tm][tn][1]);
            *(float2*)&g_h[(size_t)(r + 8) * 64 + cn] = make_float2(acc[tm][tn][2], acc[tm][tn][3]);
        }
    }
}

// ---------------- K1b: per-node attention scores ----------------
__global__ void k_att(const float* __restrict__ att_src, const float* __restrict__ att_dst) {
    int gw   = (blockIdx.x * blockDim.x + threadIdx.x) >> 5;
    int lane = threadIdx.x & 31;
    if (gw >= NN) return;
    float2 h = *(const float2*)&g_h[(size_t)gw * 64 + lane * 2];
    float s0 = __ldg(&att_src[lane * 2]), s1 = __ldg(&att_src[lane * 2 + 1]);
    float d0 = __ldg(&att_dst[lane * 2]), d1 = __ldg(&att_dst[lane * 2 + 1]);
    float ps = h.x * s0 + h.y * s1;
    float pd = h.x * d0 + h.y * d1;
    #pragma unroll
    for (int o = 16; o; o >>= 1) {
        ps += __shfl_xor_sync(0xFFFFFFFFu, ps, o);
        pd += __shfl_xor_sync(0xFFFFFFFFu, pd, o);
    }
    if (lane == 0) { g_as[gw] = ps; g_ad[gw] = pd; }
}

// ---------------- K2: in-degree histogram ----------------
__global__ void k_hist(const int* __restrict__ ei) {
    int e = blockIdx.x * blockDim.x + threadIdx.x;
    if (e < NE) atomicAdd(&g_deg[ei[NE + e]], 1);
}

// ---------------- K3: 2-level exclusive scan ----------------
__global__ void k_scanA() {
    int t = threadIdx.x;
    int i = blockIdx.x * 256 + t;
    int v = g_deg[i];
    int lane = t & 31, w = t >> 5;
    int x = v;
    #pragma unroll
    for (int d = 1; d < 32; d <<= 1) { int y = __shfl_up_sync(0xFFFFFFFFu, x, d); if (lane >= d) x += y; }
    __shared__ int wt[8];
    if (lane == 31) wt[w] = x;
    __syncthreads();
    if (t < 8) {
        int s = wt[t];
        int xs = s;
        #pragma unroll
        for (int d = 1; d < 8; d <<= 1) { int y = __shfl_up_sync(0xFFu, xs, d); if (t >= d) xs += y; }
        wt[t] = xs - s;
    }
    __syncthreads();
    int incl = x + wt[w];
    g_off[i] = incl - v;
    if (t == 255) g_bsum[blockIdx.x] = incl;
}

__global__ void k_scanB() {
    int t = threadIdx.x;
    int lane = t & 31, w = t >> 5;
    int v = g_bsum[t];
    int x = v;
    #pragma unroll
    for (int d = 1; d < 32; d <<= 1) { int y = __shfl_up_sync(0xFFFFFFFFu, x, d); if (lane >= d) x += y; }
    __shared__ int wt[32];
    if (lane == 31) wt[w] = x;
    __syncthreads();
    if (w == 0) {
        int s = wt[lane];
        int xs = s;
        #pragma unroll
        for (int d = 1; d < 32; d <<= 1) { int y = __shfl_up_sync(0xFFFFFFFFu, xs, d); if (lane >= d) xs += y; }
        wt[lane] = xs - s;
    }
    __syncthreads();
    g_bsum[t] = x - v + wt[w];
}

__global__ void k_scanC() {
    int i = blockIdx.x * 256 + threadIdx.x;
    g_off[i] += g_bsum[i >> 8];
}

// ---------------- K4: scatter into CSR ----------------
__global__ void k_scatter(const int* __restrict__ ei) {
    int e = blockIdx.x * blockDim.x + threadIdx.x;
    if (e >= NE) return;
    int dst = ei[NE + e];
    int src = ei[e];
    int p = g_off[dst] + atomicAdd(&g_fill[dst], 1);
    g_csr[p] = src;
}

// ---------------- K5: softmax aggregation + ReLU + graph-linear ----------------
__global__ __launch_bounds__(256) void k_agg(const float* __restrict__ b1,
                                             const float* __restrict__ Wlin) {
    __shared__ float s_ex[8][64];
    int lane = threadIdx.x & 31;
    int wid  = threadIdx.x >> 5;
    int node = blockIdx.x * 8 + wid;

    float ad_i = g_ad[node];
    float a0 = g_as[node] + ad_i;
    a0 = a0 >= 0.f ? a0 : NEG_SLOPE * a0;
    int deg   = g_deg[node];
    int start = g_off[node];

    float m = a0;
    for (int e = lane; e < deg; e += 32) {
        int s = g_csr[start + e];
        float a = g_as[s] + ad_i;
        a = a >= 0.f ? a : NEG_SLOPE * a;
        if (e < 64) s_ex[wid][e] = a;
        m = fmaxf(m, a);
    }
    #pragma unroll
    for (int o = 16; o; o >>= 1) m = fmaxf(m, __shfl_xor_sync(0xFFFFFFFFu, m, o));
    __syncwarp();

    float z = (lane == 0) ? __expf(a0 - m) : 0.f;
    for (int e = lane; e < deg; e += 32) {
        float a;
        if (e < 64) a = s_ex[wid][e];
        else { int s = g_csr[start + e]; a = g_as[s] + ad_i; a = a >= 0.f ? a : NEG_SLOPE * a; }
        float ex = __expf(a - m);
        if (e < 64) s_ex[wid][e] = ex;
        z += ex;
    }
    #pragma unroll
    for (int o = 16; o; o >>= 1) z += __shfl_xor_sync(0xFFFFFFFFu, z, o);
    float invz = 1.f / z;
    __syncwarp();

    float w0 = __expf(a0 - m) * invz;
    float2 hi = *(const float2*)&g_h[(size_t)node * 64 + lane * 2];
    float accx = w0 * hi.x, accy = w0 * hi.y;
    for (int e = 0; e < deg; e++) {
        int s = g_csr[start + e];
        float w;
        if (e < 64) w = s_ex[wid][e] * invz;
        else {
            float a = g_as[s] + ad_i; a = a >= 0.f ? a : NEG_SLOPE * a;
            w = __expf(a - m) * invz;
        }
        float2 hs = *(const float2*)&g_h[(size_t)s * 64 + lane * 2];
        accx = fmaf(w, hs.x, accx);
        accy = fmaf(w, hs.y, accy);
    }

    float2 bb = *(const float2*)&b1[lane * 2];
    float rx = fmaxf(accx + bb.x, 0.f);
    float ry = fmaxf(accy + bb.y, 0.f);
    int local = node & (NPG - 1);
    float2 wl = *(const float2*)&Wlin[local * 64 + lane * 2];
    float p = rx * wl.x + ry * wl.y;
    #pragma unroll
    for (int o = 16; o; o >>= 1) p += __shfl_xor_sync(0xFFFFFFFFu, p, o);
    if (lane == 0) atomicAdd(&g_logits[node >> 7], p);
}

// ---------------- K6: bias + sigmoid ----------------
__global__ void k_fin(const float* __restrict__ blin, float* __restrict__ out) {
    int i = blockIdx.x * blockDim.x + threadIdx.x;
    if (i < G_) {
        float l = g_logits[i] + blin[0];
        out[i] = 1.f / (1.f + __expf(-l));
    }
}

// ---------------- launch ----------------
extern "C" void kernel_launch(void* const* d_in, const int* in_sizes, int n_in,
                              void* d_out, int out_size) {
    const float* x    = (const float*)d_in[0];
    const int*   ei   = (const int*)  d_in[1];
    const float* W1   = (const float*)d_in[2];
    const float* asv  = (const float*)d_in[3];
    const float* adv  = (const float*)d_in[4];
    const float* b1   = (const float*)d_in[5];
    const float* Wlin = (const float*)d_in[6];
    const float* blin = (const float*)d_in[7];
    float* out = (float*)d_out;

    static cudaStream_t s2 = nullptr;
    static cudaEvent_t ev0 = nullptr, ev1 = nullptr;
    if (!s2) {
        cudaStreamCreateWithFlags(&s2, cudaStreamNonBlocking);
        cudaEventCreateWithFlags(&ev0, cudaEventDisableTiming);
        cudaEventCreateWithFlags(&ev1, cudaEventDisableTiming);
    }

    k_zero<<<NN / 256, 256>>>();

    // fork: edge preprocessing on side stream, overlapped with GEMM + att
    cudaEventRecord(ev0, 0);
    cudaStreamWaitEvent(s2, ev0, 0);
    k_hist   <<<NE / 256, 256, 0, s2>>>(ei);
    k_scanA  <<<1024, 256, 0, s2>>>();
    k_scanB  <<<1, 1024, 0, s2>>>();
    k_scanC  <<<1024, 256, 0, s2>>>();
    k_scatter<<<NE / 256, 256, 0, s2>>>(ei);
    cudaEventRecord(ev1, s2);

    k_gemm<<<NN / 128, 256>>>(x, W1);
    k_att <<<NN / 8, 256>>>(asv, adv);

    // join
    cudaStreamWaitEvent(0, ev1, 0);
    k_agg<<<NN / 8, 256>>>(b1, Wlin);
    k_fin<<<G_ / 256, 256>>>(blin, out);
}

// round 5
// speedup vs baseline: 1.5000x; 1.5000x over previous
#include <cuda_runtime.h>
#include <cstdint>

#define G_   2048
#define NPG  128
#define NN   (G_*NPG)       // 262144 nodes
#define INC  151
#define HID  64
#define NE   2097152
#define NEG_SLOPE 0.2f

// ---------------- device scratch ----------------
__device__ float g_h[(size_t)NN * HID];   // 64 MB
__device__ float g_as[NN];
__device__ float g_ad[NN];
__device__ int   g_deg[NN];
__device__ int   g_fill[NN];
__device__ int   g_off[NN];
__device__ int   g_bsum[1024];
__device__ int   g_csr[NE];

// ---------------- K0: zero counters ----------------
__global__ void k_zero() {
    int i = blockIdx.x * blockDim.x + threadIdx.x;
    g_deg[i] = 0; g_fill[i] = 0;
}

// ---------------- K1: h = x @ W1 fp32 SIMT, 8x8 microtile, fused att scores ----
// Block tile 128(M) x 64(N), 128 threads (8 tx x 16 ty), microtile (4+4)x(4+4).
#define LDX 132
#define LDW 68
__global__ __launch_bounds__(128) void k_gemm(const float* __restrict__ x,
                                              const float* __restrict__ W,
                                              const float* __restrict__ att_src,
                                              const float* __restrict__ att_dst) {
    __shared__ float sX[16 * LDX];   // [k][row], row-padded
    __shared__ float sW[16 * LDW];   // [k][col]
    int tid = threadIdx.x;
    int tx = tid & 7, ty = tid >> 3;
    int row0 = blockIdx.x * 128;

    float acc[8][8];
    #pragma unroll
    for (int i = 0; i < 8; i++)
        #pragma unroll
        for (int j = 0; j < 8; j++) acc[i][j] = 0.f;

    for (int c0 = 0; c0 < 160; c0 += 16) {
        // load x chunk transposed: sX[k][r]
        {
            int c = tid & 15, rt = tid >> 4;
            int col = c0 + c;
            bool ok = (col < INC);
            #pragma unroll
            for (int p = 0; p < 16; p++) {
                int r = rt + p * 8;
                sX[c * LDX + r] = ok ? x[(size_t)(row0 + r) * INC + col] : 0.f;
            }
        }
        // load W chunk: sW[k][n]
        {
            int n = tid & 63, kt = tid >> 6;
            #pragma unroll
            for (int p = 0; p < 8; p++) {
                int k = kt + p * 2;
                int kk = c0 + k;
                sW[k * LDW + n] = (kk < INC) ? W[kk * 64 + n] : 0.f;
            }
        }
        __syncthreads();
        #pragma unroll
        for (int k = 0; k < 16; k++) {
            float4 a0 = *(const float4*)&sX[k * LDX + ty * 4];
            float4 a1 = *(const float4*)&sX[k * LDX + 64 + ty * 4];
            float4 b0 = *(const float4*)&sW[k * LDW + tx * 4];
            float4 b1 = *(const float4*)&sW[k * LDW + 32 + tx * 4];
            float av[8] = {a0.x, a0.y, a0.z, a0.w, a1.x, a1.y, a1.z, a1.w};
            float bv[8] = {b0.x, b0.y, b0.z, b0.w, b1.x, b1.y, b1.z, b1.w};
            #pragma unroll
            for (int i = 0; i < 8; i++)
                #pragma unroll
                for (int j = 0; j < 8; j++)
                    acc[i][j] = fmaf(av[i], bv[j], acc[i][j]);
        }
        __syncthreads();
    }

    // attention vector slices for this thread's 8 columns
    float asv[8], adv[8];
    #pragma unroll
    for (int j = 0; j < 8; j++) {
        int cj = (j < 4) ? (tx * 4 + j) : (32 + tx * 4 + (j - 4));
        asv[j] = __ldg(&att_src[cj]);
        adv[j] = __ldg(&att_dst[cj]);
    }

    #pragma unroll
    for (int i = 0; i < 8; i++) {
        int r = row0 + ((i < 4) ? (ty * 4 + i) : (64 + ty * 4 + (i - 4)));
        // write h
        float4 lo = make_float4(acc[i][0], acc[i][1], acc[i][2], acc[i][3]);
        float4 hi = make_float4(acc[i][4], acc[i][5], acc[i][6], acc[i][7]);
        *(float4*)&g_h[(size_t)r * 64 + tx * 4]      = lo;
        *(float4*)&g_h[(size_t)r * 64 + 32 + tx * 4] = hi;
        // fused attention scores
        float ps = 0.f, pd = 0.f;
        #pragma unroll
        for (int j = 0; j < 8; j++) {
            ps = fmaf(acc[i][j], asv[j], ps);
            pd = fmaf(acc[i][j], adv[j], pd);
        }
        #pragma unroll
        for (int o = 4; o; o >>= 1) {
            ps += __shfl_down_sync(0xFFFFFFFFu, ps, o, 8);
            pd += __shfl_down_sync(0xFFFFFFFFu, pd, o, 8);
        }
        if (tx == 0) { g_as[r] = ps; g_ad[r] = pd; }
    }
}

// ---------------- K2: in-degree histogram ----------------
__global__ void k_hist(const int* __restrict__ ei) {
    int e = blockIdx.x * blockDim.x + threadIdx.x;
    if (e < NE) atomicAdd(&g_deg[ei[NE + e]], 1);
}

// ---------------- K3: 2-level exclusive scan ----------------
__global__ void k_scanA() {
    int t = threadIdx.x;
    int i = blockIdx.x * 256 + t;
    int v = g_deg[i];
    int lane = t & 31, w = t >> 5;
    int x = v;
    #pragma unroll
    for (int d = 1; d < 32; d <<= 1) { int y = __shfl_up_sync(0xFFFFFFFFu, x, d); if (lane >= d) x += y; }
    __shared__ int wt[8];
    if (lane == 31) wt[w] = x;
    __syncthreads();
    if (t < 8) {
        int s = wt[t];
        int xs = s;
        #pragma unroll
        for (int d = 1; d < 8; d <<= 1) { int y = __shfl_up_sync(0xFFu, xs, d); if (t >= d) xs += y; }
        wt[t] = xs - s;
    }
    __syncthreads();
    int incl = x + wt[w];
    g_off[i] = incl - v;
    if (t == 255) g_bsum[blockIdx.x] = incl;
}

__global__ void k_scanB() {
    int t = threadIdx.x;
    int lane = t & 31, w = t >> 5;
    int v = g_bsum[t];
    int x = v;
    #pragma unroll
    for (int d = 1; d < 32; d <<= 1) { int y = __shfl_up_sync(0xFFFFFFFFu, x, d); if (lane >= d) x += y; }
    __shared__ int wt[32];
    if (lane == 31) wt[w] = x;
    __syncthreads();
    if (w == 0) {
        int s = wt[lane];
        int xs = s;
        #pragma unroll
        for (int d = 1; d < 32; d <<= 1) { int y = __shfl_up_sync(0xFFFFFFFFu, xs, d); if (lane >= d) xs += y; }
        wt[lane] = xs - s;
    }
    __syncthreads();
    g_bsum[t] = x - v + wt[w];
}

__global__ void k_scanC() {
    int i = blockIdx.x * 256 + threadIdx.x;
    g_off[i] += g_bsum[i >> 8];
}

// ---------------- K4: scatter into CSR ----------------
__global__ void k_scatter(const int* __restrict__ ei) {
    int e = blockIdx.x * blockDim.x + threadIdx.x;
    if (e >= NE) return;
    int dst = ei[NE + e];
    int src = ei[e];
    int p = g_off[dst] + atomicAdd(&g_fill[dst], 1);
    g_csr[p] = src;
}

// ---------------- K5: block-per-graph softmax agg + ReLU + linear + sigmoid ----
__global__ __launch_bounds__(256) void k_agg(const float* __restrict__ b1,
                                             const float* __restrict__ Wlin,
                                             const float* __restrict__ blin,
                                             float* __restrict__ out) {
    __shared__ float sh[128 * 64];        // graph's h tile, 32 KB
    __shared__ float s_as[128], s_ad[128];
    __shared__ float s_ex[8][64];
    __shared__ float s_part[8];
    int g = blockIdx.x;
    int tid = threadIdx.x, lane = tid & 31, wid = tid >> 5;
    int nbase = g * 128;

    // stage h tile + scores
    {
        const float4* src4 = (const float4*)&g_h[(size_t)nbase * 64];
        float4* dst4 = (float4*)sh;
        #pragma unroll
        for (int i = tid; i < 128 * 16; i += 256) dst4[i] = src4[i];
        if (tid < 128) { s_as[tid] = g_as[nbase + tid]; s_ad[tid] = g_ad[nbase + tid]; }
    }
    __syncthreads();

    float2 bb = *(const float2*)&b1[lane * 2];
    float wsum = 0.f;

    for (int t = 0; t < 16; t++) {
        int ln = wid * 16 + t;          // local node
        int n  = nbase + ln;
        float ad_i = s_ad[ln];
        float a0 = s_as[ln] + ad_i;
        a0 = a0 >= 0.f ? a0 : NEG_SLOPE * a0;
        int deg = g_deg[n], start = g_off[n];

        // pass 1: max (cache raw alphas for e<64)
        float m = a0;
        for (int e = lane; e < deg; e += 32) {
            int s = g_csr[start + e] & 127;
            float a = s_as[s] + ad_i;
            a = a >= 0.f ? a : NEG_SLOPE * a;
            if (e < 64) s_ex[wid][e] = a;
            m = fmaxf(m, a);
        }
        #pragma unroll
        for (int o = 16; o; o >>= 1) m = fmaxf(m, __shfl_xor_sync(0xFFFFFFFFu, m, o));
        __syncwarp();

        // pass 2: sum of exp
        float z = (lane == 0) ? __expf(a0 - m) : 0.f;
        for (int e = lane; e < deg; e += 32) {
            float a;
            if (e < 64) a = s_ex[wid][e];
            else { int s = g_csr[start + e] & 127; a = s_as[s] + ad_i; a = a >= 0.f ? a : NEG_SLOPE * a; }
            float ex = __expf(a - m);
            if (e < 64) s_ex[wid][e] = ex;
            z += ex;
        }
        #pragma unroll
        for (int o = 16; o; o >>= 1) z += __shfl_xor_sync(0xFFFFFFFFu, z, o);
        float invz = 1.f / z;
        __syncwarp();

        // pass 3: channel-parallel accumulate from smem
        float w0 = __expf(a0 - m) * invz;
        float2 hme = *(const float2*)&sh[ln * 64 + lane * 2];
        float accx = w0 * hme.x, accy = w0 * hme.y;
        for (int e = 0; e < deg; e++) {
            int s = g_csr[start + e] & 127;
            float w;
            if (e < 64) w = s_ex[wid][e] * invz;
            else {
                float a = s_as[s] + ad_i; a = a >= 0.f ? a : NEG_SLOPE * a;
                w = __expf(a - m) * invz;
            }
            float2 hs = *(const float2*)&sh[s * 64 + lane * 2];
            accx = fmaf(w, hs.x, accx);
            accy = fmaf(w, hs.y, accy);
        }
        __syncwarp();

        // bias + ReLU + per-graph linear partial
        float rx = fmaxf(accx + bb.x, 0.f);
        float ry = fmaxf(accy + bb.y, 0.f);
        float2 wl = *(const float2*)&Wlin[ln * 64 + lane * 2];
        float p = rx * wl.x + ry * wl.y;
        #pragma unroll
        for (int o = 16; o; o >>= 1) p += __shfl_xor_sync(0xFFFFFFFFu, p, o);
        wsum += p;
    }

    if (lane == 0) s_part[wid] = wsum;
    __syncthreads();
    if (tid == 0) {
        float l = blin[0];
        #pragma unroll
        for (int i = 0; i < 8; i++) l += s_part[i];
        out[g] = 1.f / (1.f + __expf(-l));
    }
}

// ---------------- launch ----------------
extern "C" void kernel_launch(void* const* d_in, const int* in_sizes, int n_in,
                              void* d_out, int out_size) {
    const float* x    = (const float*)d_in[0];
    const int*   ei   = (const int*)  d_in[1];
    const float* W1   = (const float*)d_in[2];
    const float* asv  = (const float*)d_in[3];
    const float* adv  = (const float*)d_in[4];
    const float* b1   = (const float*)d_in[5];
    const float* Wlin = (const float*)d_in[6];
    const float* blin = (const float*)d_in[7];
    float* out = (float*)d_out;

    static cudaStream_t s2 = nullptr;
    static cudaEvent_t ev0 = nullptr, ev1 = nullptr;
    if (!s2) {
        cudaStreamCreateWithFlags(&s2, cudaStreamNonBlocking);
        cudaEventCreateWithFlags(&ev0, cudaEventDisableTiming);
        cudaEventCreateWithFlags(&ev1, cudaEventDisableTiming);
    }

    k_zero<<<NN / 256, 256>>>();

    // fork: edge preprocessing on side stream, overlapped with GEMM
    cudaEventRecord(ev0, 0);
    cudaStreamWaitEvent(s2, ev0, 0);
    k_hist   <<<NE / 256, 256, 0, s2>>>(ei);
    k_scanA  <<<1024, 256, 0, s2>>>();
    k_scanB  <<<1, 1024, 0, s2>>>();
    k_scanC  <<<1024, 256, 0, s2>>>();
    k_scatter<<<NE / 256, 256, 0, s2>>>(ei);
    cudaEventRecord(ev1, s2);

    k_gemm<<<NN / 128, 128>>>(x, W1, asv, adv);

    // join
    cudaStreamWaitEvent(0, ev1, 0);
    k_agg<<<G_, 256>>>(b1, Wlin, blin, out);
}